// round 15
// baseline (speedup 1.0000x reference)
#include <cuda_runtime.h>
#include <cuda_fp16.h>
#include <mma.h>
#include <cstdint>
#include <math.h>

using namespace nvcuda;

#define BB 4
#define SS 2048
#define DD 1024
#define GG 512
#define WW 8
#define SDIFF 2047
#define ND (BB*SDIFF)            // 8188
#define MPAD 8192

// GEMMs: fp16, CTA 128m x 256n, 256 thr (8 warps, warp tile 64x64), K-chunk 64, 3-stage.
#define LDA1 72                  // fp16 elems (144B rows)
#define BUF1 55296               // 128*144 + 256*144
#define LDC1 260
#define SMEM1 165888             // 3*BUF1 (> epilogue 128*260*4=133120)

#define CP_ASYNC16(dst, src) \
    asm volatile("cp.async.cg.shared.global [%0], [%1], 16;" :: "r"(dst), "l"(src))
#define CP_COMMIT() asm volatile("cp.async.commit_group;" ::: "memory")
#define CP_WAIT1() asm volatile("cp.async.wait_group 1;" ::: "memory")
#define CP_WAIT0() asm volatile("cp.async.wait_group 0;" ::: "memory")

__device__ __forceinline__ uint32_t smem_u32(const void* p) {
    uint32_t a;
    asm("{ .reg .u64 t; cvta.to.shared.u64 t, %1; cvt.u32.u64 %0, t; }" : "=r"(a) : "l"(p));
    return a;
}

// ---------------- global scratch ----------------
__device__ __half  d_gh[GG * DD];              // guid/||g|| fp16 [g][k]
__device__ __half  d_gth[DD * GG];             // guid^T fp16 [d][g]
__device__ __half  d_nh[(size_t)MPAD * DD];    // normed fp16 [r][k]
__device__ float   d_mw[MPAD];                 // tanh(2*mag)
__device__ __half  d_wh[(size_t)MPAD * GG];    // exp(2*sims) fp16 [r][g]
__device__ float   d_sums[MPAD];               // row sums of exp (f32)
__device__ __half  d_blh[(size_t)MPAD * DD];   // blended fp16 [r][d]

// ---------------- fused prep: gprep (512) + gt (512) + diff-prep (1024) ----------------
__global__ void __launch_bounds__(256) k_fused(const float* __restrict__ emb,
                                               const float* __restrict__ guid) {
    int bid = blockIdx.x;
    int tid = threadIdx.x;
    if (bid < 512) {
        int g = bid;
        const float4* row = (const float4*)(guid + (size_t)g * DD);
        float4 x = row[tid];
        float s = x.x*x.x + x.y*x.y + x.z*x.z + x.w*x.w;
        #pragma unroll
        for (int o = 16; o; o >>= 1) s += __shfl_xor_sync(0xffffffffu, s, o);
        __shared__ float red[8];
        __shared__ float sinv;
        if ((tid & 31) == 0) red[tid >> 5] = s;
        __syncthreads();
        if (tid == 0) {
            float t = 0.f;
            #pragma unroll
            for (int i = 0; i < 8; i++) t += red[i];
            sinv = 1.0f / fmaxf(sqrtf(t), 1e-8f);
        }
        __syncthreads();
        float inv = sinv;
        __half2* o1 = (__half2*)(d_gh + (size_t)g * DD);
        o1[2*tid]   = __floats2half2_rn(x.x * inv, x.y * inv);
        o1[2*tid+1] = __floats2half2_rn(x.z * inv, x.w * inv);
    } else if (bid < 1024) {
        __shared__ float tile[32][33];
        int lb = bid - 512;
        int d0 = (lb & 31) * 32, g0 = (lb >> 5) * 32;
        int tx = tid & 31, ty = tid >> 5;
        #pragma unroll
        for (int yy = ty; yy < 32; yy += 8)
            tile[yy][tx] = guid[(size_t)(g0 + yy) * DD + (d0 + tx)];
        __syncthreads();
        #pragma unroll
        for (int yy = ty; yy < 32; yy += 8)
            d_gth[(size_t)(d0 + yy) * GG + (g0 + tx)] = __float2half_rn(tile[tx][yy]);
    } else {
        int lane = tid & 31, wid = tid >> 5;
        int r = (bid - 1024) * 8 + wid;
        if (lane == 0) d_sums[r] = 0.f;
        __half2* nb = (__half2*)(d_nh + (size_t)r * DD);
        if (r >= ND) {
            __half2 z = __floats2half2_rn(0.f, 0.f);
            #pragma unroll
            for (int it = 0; it < 8; it++) {
                int v = lane + 32 * it;
                nb[2*v] = z; nb[2*v+1] = z;
            }
            if (lane == 0) d_mw[r] = 0.f;
            return;
        }
        int b = r / SDIFF;
        int i = r - b * SDIFF;
        const float4* e0 = (const float4*)(emb + ((size_t)b * SS + i) * DD);
        float4 df[8];
        float ssq = 0.f;
        #pragma unroll
        for (int it = 0; it < 8; it++) {
            int v = lane + 32 * it;
            float4 a = e0[v + DD/4];
            float4 c = e0[v];
            df[it].x = a.x - c.x; df[it].y = a.y - c.y;
            df[it].z = a.z - c.z; df[it].w = a.w - c.w;
            ssq += df[it].x*df[it].x + df[it].y*df[it].y + df[it].z*df[it].z + df[it].w*df[it].w;
        }
        #pragma unroll
        for (int o = 16; o; o >>= 1) ssq += __shfl_xor_sync(0xffffffffu, ssq, o);
        float mag = sqrtf(ssq);
        float scale = (mag > 1e-6f) ? (1.0f / mag) : 0.0f;
        if (lane == 0) d_mw[r] = tanhf(2.0f * mag);
        #pragma unroll
        for (int it = 0; it < 8; it++) {
            int v = lane + 32 * it;
            nb[2*v]   = __floats2half2_rn(df[it].x * scale, df[it].y * scale);
            nb[2*v+1] = __floats2half2_rn(df[it].z * scale, df[it].w * scale);
        }
    }
}

// ---------------- mm1: sims = normed x gh^T (fp16) + exp epilogue ----------------
__global__ void __launch_bounds__(256, 1) k_mm1() {
    extern __shared__ __align__(128) char smem[];
    uint32_t sbase = smem_u32(smem);
    int tid = threadIdx.x, wid = tid >> 5;
    int wm = wid >> 2, wn = wid & 3;
    int m0 = blockIdx.x * 128, n0 = blockIdx.y * 256;

    wmma::fragment<wmma::accumulator, 16, 16, 16, float> acc[4][4];
    #pragma unroll
    for (int mi = 0; mi < 4; mi++)
        #pragma unroll
        for (int ni = 0; ni < 4; ni++)
            wmma::fill_fragment(acc[mi][ni], 0.0f);

    auto load_chunk = [&](int kc, int buf) {
        uint32_t ab = sbase + buf * BUF1;
        #pragma unroll
        for (int i = 0; i < 4; i++) {
            int q = tid + i * 256;
            int r = q >> 3, v = q & 7;
            const char* src = (const char*)d_nh + ((size_t)(m0 + r) * DD + kc * 64 + v * 8) * 2;
            CP_ASYNC16(ab + r * 144 + v * 16, src);
        }
        uint32_t bb = ab + 18432;
        #pragma unroll
        for (int i = 0; i < 8; i++) {
            int q = tid + i * 256;
            int r = q >> 3, v = q & 7;
            const char* src = (const char*)d_gh + ((size_t)(n0 + r) * DD + kc * 64 + v * 8) * 2;
            CP_ASYNC16(bb + r * 144 + v * 16, src);
        }
        CP_COMMIT();
    };

    load_chunk(0, 0);
    load_chunk(1, 1);
    for (int kc = 0; kc < 16; kc++) {
        CP_WAIT1();
        __syncthreads();
        if (kc + 2 < 16) load_chunk(kc + 2, (kc + 2) % 3);
        const __half* As = (const __half*)(smem + (kc % 3) * BUF1);
        const __half* Bs = As + 9216;
        #pragma unroll
        for (int ks = 0; ks < 4; ks++) {
            wmma::fragment<wmma::matrix_a, 16, 16, 16, __half, wmma::row_major> af[4];
            wmma::fragment<wmma::matrix_b, 16, 16, 16, __half, wmma::col_major> bf[4];
            #pragma unroll
            for (int mi = 0; mi < 4; mi++)
                wmma::load_matrix_sync(af[mi], As + (wm*64 + mi*16) * LDA1 + ks*16, LDA1);
            #pragma unroll
            for (int ni = 0; ni < 4; ni++)
                wmma::load_matrix_sync(bf[ni], Bs + (wn*64 + ni*16) * LDA1 + ks*16, LDA1);
            #pragma unroll
            for (int mi = 0; mi < 4; mi++)
                #pragma unroll
                for (int ni = 0; ni < 4; ni++)
                    wmma::mma_sync(acc[mi][ni], af[mi], bf[ni], acc[mi][ni]);
        }
    }
    CP_WAIT0();
    __syncthreads();
    float* Cs = (float*)smem;   // [128][LDC1]
    #pragma unroll
    for (int mi = 0; mi < 4; mi++)
        #pragma unroll
        for (int ni = 0; ni < 4; ni++)
            wmma::store_matrix_sync(Cs + (wm*64 + mi*16) * LDC1 + wn*64 + ni*16,
                                    acc[mi][ni], LDC1, wmma::mem_row_major);
    __syncthreads();

    int row = tid >> 1, c0 = (tid & 1) * 128;
    float sum = 0.f;
    __half2* wout = (__half2*)(d_wh + (size_t)(m0 + row) * GG + n0 + c0);
    #pragma unroll 8
    for (int j = 0; j < 128; j += 4) {
        float e0 = __expf(2.0f * Cs[row * LDC1 + c0 + j + 0]);
        float e1 = __expf(2.0f * Cs[row * LDC1 + c0 + j + 1]);
        float e2 = __expf(2.0f * Cs[row * LDC1 + c0 + j + 2]);
        float e3 = __expf(2.0f * Cs[row * LDC1 + c0 + j + 3]);
        sum += e0 + e1 + e2 + e3;
        wout[(j >> 1) + 0] = __floats2half2_rn(e0, e1);
        wout[(j >> 1) + 1] = __floats2half2_rn(e2, e3);
    }
    atomicAdd(&d_sums[m0 + row], sum);
}

// ---------------- mm2: influence = wh x gth^T (fp16) + blend epilogue (fp16 out) ----------------
__global__ void __launch_bounds__(256, 1) k_mm2() {
    extern __shared__ __align__(128) char smem[];
    uint32_t sbase = smem_u32(smem);
    int tid = threadIdx.x, wid = tid >> 5;
    int wm = wid >> 2, wn = wid & 3;
    int m0 = blockIdx.x * 128, n0 = blockIdx.y * 256;

    wmma::fragment<wmma::accumulator, 16, 16, 16, float> acc[4][4];
    #pragma unroll
    for (int mi = 0; mi < 4; mi++)
        #pragma unroll
        for (int ni = 0; ni < 4; ni++)
            wmma::fill_fragment(acc[mi][ni], 0.0f);

    auto load_chunk = [&](int kc, int buf) {
        uint32_t ab = sbase + buf * BUF1;
        #pragma unroll
        for (int i = 0; i < 4; i++) {
            int q = tid + i * 256;
            int r = q >> 3, v = q & 7;
            const char* src = (const char*)d_wh + ((size_t)(m0 + r) * GG + kc * 64 + v * 8) * 2;
            CP_ASYNC16(ab + r * 144 + v * 16, src);
        }
        uint32_t bb = ab + 18432;
        #pragma unroll
        for (int i = 0; i < 8; i++) {
            int q = tid + i * 256;
            int r = q >> 3, v = q & 7;
            const char* src = (const char*)d_gth + ((size_t)(n0 + r) * GG + kc * 64 + v * 8) * 2;
            CP_ASYNC16(bb + r * 144 + v * 16, src);
        }
        CP_COMMIT();
    };

    load_chunk(0, 0);
    load_chunk(1, 1);
    for (int kc = 0; kc < 8; kc++) {
        CP_WAIT1();
        __syncthreads();
        if (kc + 2 < 8) load_chunk(kc + 2, (kc + 2) % 3);
        const __half* As = (const __half*)(smem + (kc % 3) * BUF1);
        const __half* Bs = As + 9216;
        #pragma unroll
        for (int ks = 0; ks < 4; ks++) {
            wmma::fragment<wmma::matrix_a, 16, 16, 16, __half, wmma::row_major> af[4];
            wmma::fragment<wmma::matrix_b, 16, 16, 16, __half, wmma::col_major> bf[4];
            #pragma unroll
            for (int mi = 0; mi < 4; mi++)
                wmma::load_matrix_sync(af[mi], As + (wm*64 + mi*16) * LDA1 + ks*16, LDA1);
            #pragma unroll
            for (int ni = 0; ni < 4; ni++)
                wmma::load_matrix_sync(bf[ni], Bs + (wn*64 + ni*16) * LDA1 + ks*16, LDA1);
            #pragma unroll
            for (int mi = 0; mi < 4; mi++)
                #pragma unroll
                for (int ni = 0; ni < 4; ni++)
                    wmma::mma_sync(acc[mi][ni], af[mi], bf[ni], acc[mi][ni]);
        }
    }
    CP_WAIT0();
    __syncthreads();
    float* Cs = (float*)smem;   // [128][LDC1]
    #pragma unroll
    for (int mi = 0; mi < 4; mi++)
        #pragma unroll
        for (int ni = 0; ni < 4; ni++)
            wmma::store_matrix_sync(Cs + (wm*64 + mi*16) * LDC1 + wn*64 + ni*16,
                                    acc[mi][ni], LDC1, wmma::mem_row_major);
    __syncthreads();

    int row = tid >> 1, c0 = (tid & 1) * 128;
    int r = m0 + row;
    if (r < ND) {
        float sc = 0.4f / d_sums[r];
        const __half2* nh2 = (const __half2*)(d_nh + (size_t)r * DD + n0 + c0);
        uint2* ob = (uint2*)(d_blh + (size_t)r * DD + n0 + c0);
        #pragma unroll 8
        for (int j = 0; j < 32; j++) {
            float4 c = *(const float4*)&Cs[row * LDC1 + c0 + j * 4];
            float2 f0 = __half22float2(nh2[2*j]);
            float2 f1 = __half22float2(nh2[2*j+1]);
            __half2 h0 = __floats2half2_rn(0.6f * f0.x + sc * c.x, 0.6f * f0.y + sc * c.y);
            __half2 h1 = __floats2half2_rn(0.6f * f1.x + sc * c.z, 0.6f * f1.y + sc * c.w);
            uint2 u;
            u.x = *(uint32_t*)&h0;
            u.y = *(uint32_t*)&h1;
            ob[j] = u;
        }
    }
}

// ---------------- windowed weighted blend into output (fp16 smem, precomputed weights) ----------------
// grid (256, 4): x = 32-position group (4 batches x 64 groups), y = 256-elem d-slice.
__global__ void __launch_bounds__(256) k_out(float* __restrict__ out) {
    __shared__ uint2 sm[39][64];      // 39 rows x 256 halves
    __shared__ float smw[39];
    __shared__ float smc[32][WW];     // per-row tap weights
    __shared__ float sminv[32];       // per-row 1/wsum
    int tid = threadIdx.x;
    int b = blockIdx.x >> 6;
    int p0 = (blockIdx.x & 63) * 32;
    int base = b * SDIFF;
    int dh = blockIdx.y * 256;        // half offset within row

    // stage 39 blended row-slices + mw taps (rows p0-8 .. p0+30, clamped)
    #pragma unroll
    for (int i = 0; i < 5; i++) {
        int q = tid + i * 256;
        if (q < 39 * 32) {
            int j = q >> 5, col = q & 31;
            int rr = p0 - 8 + j;
            int gr = base + (rr < 0 ? 0 : rr);
            uint4 v = ((const uint4*)d_blh)[((size_t)gr * DD + dh) / 8 + col];
            sm[j][2*col]   = make_uint2(v.x, v.y);
            sm[j][2*col+1] = make_uint2(v.z, v.w);
        }
    }
    if (tid < 39) {
        int rr = p0 - 8 + tid;
        smw[tid] = d_mw[base + (rr < 0 ? 0 : rr)];
    }
    __syncthreads();

    // phase 0b: per-row weights (256 threads cover 32 rows x 8 taps)
    {
        int pl = tid >> 3, k = tid & 7;
        int p = p0 + pl;
        int idx = p - WW + k;
        float ck = 0.f;
        if (p >= 1 && idx >= 0) {
            int w = (p < WW) ? p : WW;
            int j = k - (WW - w);
            float lin = (w > 1) ? (0.1f + 0.9f * (float)j / (float)(w - 1)) : 0.1f;
            ck = lin * smw[pl + k];
        }
        smc[pl][k] = ck;
    }
    __syncthreads();
    if (tid < 32) {
        float ws = 0.f;
        #pragma unroll
        for (int k = 0; k < WW; k++) ws += smc[tid][k];
        sminv[tid] = 1.0f / fmaxf(ws, 1e-8f);
    }
    __syncthreads();

    #pragma unroll
    for (int i = 0; i < 8; i++) {
        int item = i * 256 + tid;
        int pl = item >> 6, col = item & 63;
        int p = p0 + pl;
        float inv = sminv[pl];
        float4 o = make_float4(0.f, 0.f, 0.f, 0.f);
        #pragma unroll
        for (int k = 0; k < WW; k++) {
            float ck = smc[pl][k];
            uint2 u = sm[pl + k][col];
            float2 fa = __half22float2(*(__half2*)&u.x);
            float2 fb = __half22float2(*(__half2*)&u.y);
            o.x = fmaf(ck, fa.x, o.x);
            o.y = fmaf(ck, fa.y, o.y);
            o.z = fmaf(ck, fb.x, o.z);
            o.w = fmaf(ck, fb.y, o.w);
        }
        o.x *= inv; o.y *= inv; o.z *= inv; o.w *= inv;
        ((float4*)out)[(size_t)(b * SS + p) * 256 + (dh >> 2) + col] = o;
    }
}

extern "C" void kernel_launch(void* const* d_in, const int* in_sizes, int n_in,
                              void* d_out, int out_size) {
    (void)in_sizes; (void)n_in; (void)out_size;
    const float* emb  = (const float*)d_in[0];
    const float* guid = (const float*)d_in[1];
    float* out = (float*)d_out;

    cudaFuncSetAttribute(k_mm1, cudaFuncAttributeMaxDynamicSharedMemorySize, SMEM1);
    cudaFuncSetAttribute(k_mm2, cudaFuncAttributeMaxDynamicSharedMemorySize, SMEM1);

    k_fused<<<2048, 256>>>(emb, guid);
    k_mm1<<<dim3(64, 2), 256, SMEM1>>>();
    k_mm2<<<dim3(64, 4), 256, SMEM1>>>();
    k_out<<<dim3(256, 4), 256>>>(out);
}

// round 16
// speedup vs baseline: 1.0014x; 1.0014x over previous
#include <cuda_runtime.h>
#include <cuda_fp16.h>
#include <mma.h>
#include <cstdint>
#include <math.h>

using namespace nvcuda;

#define BB 4
#define SS 2048
#define DD 1024
#define GG 512
#define WW 8
#define SDIFF 2047
#define ND (BB*SDIFF)            // 8188
#define MPAD 8192

// GEMMs: fp16, CTA 128m x 256n, 256 thr (8 warps, warp tile 64x64), K-chunk 64, 3-stage.
#define LDA1 72                  // fp16 elems (144B rows)
#define BUF1 55296               // 128*144 + 256*144
#define LDC1 260
#define SMEM1 165888             // 3*BUF1 (> epilogue 128*260*4=133120)

#define CP_ASYNC16(dst, src) \
    asm volatile("cp.async.cg.shared.global [%0], [%1], 16;" :: "r"(dst), "l"(src))
#define CP_COMMIT() asm volatile("cp.async.commit_group;" ::: "memory")
#define CP_WAIT1() asm volatile("cp.async.wait_group 1;" ::: "memory")
#define CP_WAIT0() asm volatile("cp.async.wait_group 0;" ::: "memory")

__device__ __forceinline__ uint32_t smem_u32(const void* p) {
    uint32_t a;
    asm("{ .reg .u64 t; cvta.to.shared.u64 t, %1; cvt.u32.u64 %0, t; }" : "=r"(a) : "l"(p));
    return a;
}

// ---------------- global scratch ----------------
__device__ __half  d_gh[GG * DD];              // guid/||g|| fp16 [g][k]
__device__ __half  d_gth[DD * GG];             // guid^T fp16 [d][g]
__device__ __half  d_nh[(size_t)MPAD * DD];    // normed fp16 [r][k]
__device__ float   d_mw[MPAD];                 // tanh(2*mag)
__device__ __half  d_wh[(size_t)MPAD * GG];    // exp(2*sims) fp16 [r][g]
__device__ float   d_sums[MPAD];               // row sums of exp (f32)
__device__ __half  d_blh[(size_t)MPAD * DD];   // blended fp16 [r][d]

// ---------------- fused prep: gprep (512) + gt (512) + diff-prep (1024) ----------------
__global__ void __launch_bounds__(256) k_fused(const float* __restrict__ emb,
                                               const float* __restrict__ guid) {
    int bid = blockIdx.x;
    int tid = threadIdx.x;
    if (bid < 512) {
        int g = bid;
        const float4* row = (const float4*)(guid + (size_t)g * DD);
        float4 x = row[tid];
        float s = x.x*x.x + x.y*x.y + x.z*x.z + x.w*x.w;
        #pragma unroll
        for (int o = 16; o; o >>= 1) s += __shfl_xor_sync(0xffffffffu, s, o);
        __shared__ float red[8];
        __shared__ float sinv;
        if ((tid & 31) == 0) red[tid >> 5] = s;
        __syncthreads();
        if (tid == 0) {
            float t = 0.f;
            #pragma unroll
            for (int i = 0; i < 8; i++) t += red[i];
            sinv = 1.0f / fmaxf(sqrtf(t), 1e-8f);
        }
        __syncthreads();
        float inv = sinv;
        __half2* o1 = (__half2*)(d_gh + (size_t)g * DD);
        o1[2*tid]   = __floats2half2_rn(x.x * inv, x.y * inv);
        o1[2*tid+1] = __floats2half2_rn(x.z * inv, x.w * inv);
    } else if (bid < 1024) {
        __shared__ float tile[32][33];
        int lb = bid - 512;
        int d0 = (lb & 31) * 32, g0 = (lb >> 5) * 32;
        int tx = tid & 31, ty = tid >> 5;
        #pragma unroll
        for (int yy = ty; yy < 32; yy += 8)
            tile[yy][tx] = guid[(size_t)(g0 + yy) * DD + (d0 + tx)];
        __syncthreads();
        #pragma unroll
        for (int yy = ty; yy < 32; yy += 8)
            d_gth[(size_t)(d0 + yy) * GG + (g0 + tx)] = __float2half_rn(tile[tx][yy]);
    } else {
        int lane = tid & 31, wid = tid >> 5;
        int r = (bid - 1024) * 8 + wid;
        if (lane == 0) d_sums[r] = 0.f;
        __half2* nb = (__half2*)(d_nh + (size_t)r * DD);
        if (r >= ND) {
            __half2 z = __floats2half2_rn(0.f, 0.f);
            #pragma unroll
            for (int it = 0; it < 8; it++) {
                int v = lane + 32 * it;
                nb[2*v] = z; nb[2*v+1] = z;
            }
            if (lane == 0) d_mw[r] = 0.f;
            return;
        }
        int b = r / SDIFF;
        int i = r - b * SDIFF;
        const float4* e0 = (const float4*)(emb + ((size_t)b * SS + i) * DD);
        float4 df[8];
        float ssq = 0.f;
        #pragma unroll
        for (int it = 0; it < 8; it++) {
            int v = lane + 32 * it;
            float4 a = e0[v + DD/4];
            float4 c = e0[v];
            df[it].x = a.x - c.x; df[it].y = a.y - c.y;
            df[it].z = a.z - c.z; df[it].w = a.w - c.w;
            ssq += df[it].x*df[it].x + df[it].y*df[it].y + df[it].z*df[it].z + df[it].w*df[it].w;
        }
        #pragma unroll
        for (int o = 16; o; o >>= 1) ssq += __shfl_xor_sync(0xffffffffu, ssq, o);
        float mag = sqrtf(ssq);
        float scale = (mag > 1e-6f) ? (1.0f / mag) : 0.0f;
        if (lane == 0) d_mw[r] = tanhf(2.0f * mag);
        #pragma unroll
        for (int it = 0; it < 8; it++) {
            int v = lane + 32 * it;
            nb[2*v]   = __floats2half2_rn(df[it].x * scale, df[it].y * scale);
            nb[2*v+1] = __floats2half2_rn(df[it].z * scale, df[it].w * scale);
        }
    }
}

// ---------------- mm1: sims = normed x gh^T (fp16) + exp epilogue ----------------
__global__ void __launch_bounds__(256, 1) k_mm1() {
    extern __shared__ __align__(128) char smem[];
    uint32_t sbase = smem_u32(smem);
    int tid = threadIdx.x, wid = tid >> 5;
    int wm = wid >> 2, wn = wid & 3;
    int m0 = blockIdx.x * 128, n0 = blockIdx.y * 256;

    wmma::fragment<wmma::accumulator, 16, 16, 16, float> acc[4][4];
    #pragma unroll
    for (int mi = 0; mi < 4; mi++)
        #pragma unroll
        for (int ni = 0; ni < 4; ni++)
            wmma::fill_fragment(acc[mi][ni], 0.0f);

    auto load_chunk = [&](int kc, int buf) {
        uint32_t ab = sbase + buf * BUF1;
        #pragma unroll
        for (int i = 0; i < 4; i++) {
            int q = tid + i * 256;
            int r = q >> 3, v = q & 7;
            const char* src = (const char*)d_nh + ((size_t)(m0 + r) * DD + kc * 64 + v * 8) * 2;
            CP_ASYNC16(ab + r * 144 + v * 16, src);
        }
        uint32_t bb = ab + 18432;
        #pragma unroll
        for (int i = 0; i < 8; i++) {
            int q = tid + i * 256;
            int r = q >> 3, v = q & 7;
            const char* src = (const char*)d_gh + ((size_t)(n0 + r) * DD + kc * 64 + v * 8) * 2;
            CP_ASYNC16(bb + r * 144 + v * 16, src);
        }
        CP_COMMIT();
    };

    load_chunk(0, 0);
    load_chunk(1, 1);
    for (int kc = 0; kc < 16; kc++) {
        CP_WAIT1();
        __syncthreads();
        if (kc + 2 < 16) load_chunk(kc + 2, (kc + 2) % 3);
        const __half* As = (const __half*)(smem + (kc % 3) * BUF1);
        const __half* Bs = As + 9216;
        #pragma unroll
        for (int ks = 0; ks < 4; ks++) {
            wmma::fragment<wmma::matrix_a, 16, 16, 16, __half, wmma::row_major> af[4];
            wmma::fragment<wmma::matrix_b, 16, 16, 16, __half, wmma::col_major> bf[4];
            #pragma unroll
            for (int mi = 0; mi < 4; mi++)
                wmma::load_matrix_sync(af[mi], As + (wm*64 + mi*16) * LDA1 + ks*16, LDA1);
            #pragma unroll
            for (int ni = 0; ni < 4; ni++)
                wmma::load_matrix_sync(bf[ni], Bs + (wn*64 + ni*16) * LDA1 + ks*16, LDA1);
            #pragma unroll
            for (int mi = 0; mi < 4; mi++)
                #pragma unroll
                for (int ni = 0; ni < 4; ni++)
                    wmma::mma_sync(acc[mi][ni], af[mi], bf[ni], acc[mi][ni]);
        }
    }
    CP_WAIT0();
    __syncthreads();
    float* Cs = (float*)smem;   // [128][LDC1]
    #pragma unroll
    for (int mi = 0; mi < 4; mi++)
        #pragma unroll
        for (int ni = 0; ni < 4; ni++)
            wmma::store_matrix_sync(Cs + (wm*64 + mi*16) * LDC1 + wn*64 + ni*16,
                                    acc[mi][ni], LDC1, wmma::mem_row_major);
    __syncthreads();

    int row = tid >> 1, c0 = (tid & 1) * 128;
    float sum = 0.f;
    __half2* wout = (__half2*)(d_wh + (size_t)(m0 + row) * GG + n0 + c0);
    #pragma unroll 8
    for (int j = 0; j < 128; j += 4) {
        float e0 = __expf(2.0f * Cs[row * LDC1 + c0 + j + 0]);
        float e1 = __expf(2.0f * Cs[row * LDC1 + c0 + j + 1]);
        float e2 = __expf(2.0f * Cs[row * LDC1 + c0 + j + 2]);
        float e3 = __expf(2.0f * Cs[row * LDC1 + c0 + j + 3]);
        sum += e0 + e1 + e2 + e3;
        wout[(j >> 1) + 0] = __floats2half2_rn(e0, e1);
        wout[(j >> 1) + 1] = __floats2half2_rn(e2, e3);
    }
    atomicAdd(&d_sums[m0 + row], sum);
}

// ---------------- mm2: influence = wh x gth^T (fp16) + blend epilogue (fp16 out) ----------------
__global__ void __launch_bounds__(256, 1) k_mm2() {
    extern __shared__ __align__(128) char smem[];
    uint32_t sbase = smem_u32(smem);
    int tid = threadIdx.x, wid = tid >> 5;
    int wm = wid >> 2, wn = wid & 3;
    int m0 = blockIdx.x * 128, n0 = blockIdx.y * 256;

    wmma::fragment<wmma::accumulator, 16, 16, 16, float> acc[4][4];
    #pragma unroll
    for (int mi = 0; mi < 4; mi++)
        #pragma unroll
        for (int ni = 0; ni < 4; ni++)
            wmma::fill_fragment(acc[mi][ni], 0.0f);

    auto load_chunk = [&](int kc, int buf) {
        uint32_t ab = sbase + buf * BUF1;
        #pragma unroll
        for (int i = 0; i < 4; i++) {
            int q = tid + i * 256;
            int r = q >> 3, v = q & 7;
            const char* src = (const char*)d_wh + ((size_t)(m0 + r) * GG + kc * 64 + v * 8) * 2;
            CP_ASYNC16(ab + r * 144 + v * 16, src);
        }
        uint32_t bb = ab + 18432;
        #pragma unroll
        for (int i = 0; i < 8; i++) {
            int q = tid + i * 256;
            int r = q >> 3, v = q & 7;
            const char* src = (const char*)d_gth + ((size_t)(n0 + r) * GG + kc * 64 + v * 8) * 2;
            CP_ASYNC16(bb + r * 144 + v * 16, src);
        }
        CP_COMMIT();
    };

    load_chunk(0, 0);
    load_chunk(1, 1);
    for (int kc = 0; kc < 8; kc++) {
        CP_WAIT1();
        __syncthreads();
        if (kc + 2 < 8) load_chunk(kc + 2, (kc + 2) % 3);
        const __half* As = (const __half*)(smem + (kc % 3) * BUF1);
        const __half* Bs = As + 9216;
        #pragma unroll
        for (int ks = 0; ks < 4; ks++) {
            wmma::fragment<wmma::matrix_a, 16, 16, 16, __half, wmma::row_major> af[4];
            wmma::fragment<wmma::matrix_b, 16, 16, 16, __half, wmma::col_major> bf[4];
            #pragma unroll
            for (int mi = 0; mi < 4; mi++)
                wmma::load_matrix_sync(af[mi], As + (wm*64 + mi*16) * LDA1 + ks*16, LDA1);
            #pragma unroll
            for (int ni = 0; ni < 4; ni++)
                wmma::load_matrix_sync(bf[ni], Bs + (wn*64 + ni*16) * LDA1 + ks*16, LDA1);
            #pragma unroll
            for (int mi = 0; mi < 4; mi++)
                #pragma unroll
                for (int ni = 0; ni < 4; ni++)
                    wmma::mma_sync(acc[mi][ni], af[mi], bf[ni], acc[mi][ni]);
        }
    }
    CP_WAIT0();
    __syncthreads();
    float* Cs = (float*)smem;   // [128][LDC1]
    #pragma unroll
    for (int mi = 0; mi < 4; mi++)
        #pragma unroll
        for (int ni = 0; ni < 4; ni++)
            wmma::store_matrix_sync(Cs + (wm*64 + mi*16) * LDC1 + wn*64 + ni*16,
                                    acc[mi][ni], LDC1, wmma::mem_row_major);
    __syncthreads();

    int row = tid >> 1, c0 = (tid & 1) * 128;
    int r = m0 + row;
    if (r < ND) {
        float sc = 0.4f / d_sums[r];
        const __half2* nh2 = (const __half2*)(d_nh + (size_t)r * DD + n0 + c0);
        uint2* ob = (uint2*)(d_blh + (size_t)r * DD + n0 + c0);
        #pragma unroll 8
        for (int j = 0; j < 32; j++) {
            float4 c = *(const float4*)&Cs[row * LDC1 + c0 + j * 4];
            float2 f0 = __half22float2(nh2[2*j]);
            float2 f1 = __half22float2(nh2[2*j+1]);
            __half2 h0 = __floats2half2_rn(0.6f * f0.x + sc * c.x, 0.6f * f0.y + sc * c.y);
            __half2 h1 = __floats2half2_rn(0.6f * f1.x + sc * c.z, 0.6f * f1.y + sc * c.w);
            uint2 u;
            u.x = *(uint32_t*)&h0;
            u.y = *(uint32_t*)&h1;
            ob[j] = u;
        }
    }
}

// ---------------- windowed weighted blend into output (fp16 smem, precomputed weights) ----------------
// grid (256, 4): x = 32-position group (4 batches x 64 groups), y = 256-elem d-slice.
__global__ void __launch_bounds__(256) k_out(float* __restrict__ out) {
    __shared__ uint2 sm[39][64];      // 39 rows x 256 halves
    __shared__ float smw[39];
    __shared__ float smc[32][WW];     // per-row tap weights
    __shared__ float sminv[32];       // per-row 1/wsum
    int tid = threadIdx.x;
    int b = blockIdx.x >> 6;
    int p0 = (blockIdx.x & 63) * 32;
    int base = b * SDIFF;
    int dh = blockIdx.y * 256;        // half offset within row

    // stage 39 blended row-slices + mw taps (rows p0-8 .. p0+30, clamped)
    #pragma unroll
    for (int i = 0; i < 5; i++) {
        int q = tid + i * 256;
        if (q < 39 * 32) {
            int j = q >> 5, col = q & 31;
            int rr = p0 - 8 + j;
            int gr = base + (rr < 0 ? 0 : rr);
            uint4 v = ((const uint4*)d_blh)[((size_t)gr * DD + dh) / 8 + col];
            sm[j][2*col]   = make_uint2(v.x, v.y);
            sm[j][2*col+1] = make_uint2(v.z, v.w);
        }
    }
    if (tid < 39) {
        int rr = p0 - 8 + tid;
        smw[tid] = d_mw[base + (rr < 0 ? 0 : rr)];
    }
    __syncthreads();

    // phase 0b: per-row weights (256 threads cover 32 rows x 8 taps)
    {
        int pl = tid >> 3, k = tid & 7;
        int p = p0 + pl;
        int idx = p - WW + k;
        float ck = 0.f;
        if (p >= 1 && idx >= 0) {
            int w = (p < WW) ? p : WW;
            int j = k - (WW - w);
            float lin = (w > 1) ? (0.1f + 0.9f * (float)j / (float)(w - 1)) : 0.1f;
            ck = lin * smw[pl + k];
        }
        smc[pl][k] = ck;
    }
    __syncthreads();
    if (tid < 32) {
        float ws = 0.f;
        #pragma unroll
        for (int k = 0; k < WW; k++) ws += smc[tid][k];
        sminv[tid] = 1.0f / fmaxf(ws, 1e-8f);
    }
    __syncthreads();

    #pragma unroll
    for (int i = 0; i < 8; i++) {
        int item = i * 256 + tid;
        int pl = item >> 6, col = item & 63;
        int p = p0 + pl;
        float inv = sminv[pl];
        float4 o = make_float4(0.f, 0.f, 0.f, 0.f);
        #pragma unroll
        for (int k = 0; k < WW; k++) {
            float ck = smc[pl][k];
            uint2 u = sm[pl + k][col];
            float2 fa = __half22float2(*(__half2*)&u.x);
            float2 fb = __half22float2(*(__half2*)&u.y);
            o.x = fmaf(ck, fa.x, o.x);
            o.y = fmaf(ck, fa.y, o.y);
            o.z = fmaf(ck, fb.x, o.z);
            o.w = fmaf(ck, fb.y, o.w);
        }
        o.x *= inv; o.y *= inv; o.z *= inv; o.w *= inv;
        ((float4*)out)[(size_t)(b * SS + p) * 256 + (dh >> 2) + col] = o;
    }
}

extern "C" void kernel_launch(void* const* d_in, const int* in_sizes, int n_in,
                              void* d_out, int out_size) {
    (void)in_sizes; (void)n_in; (void)out_size;
    const float* emb  = (const float*)d_in[0];
    const float* guid = (const float*)d_in[1];
    float* out = (float*)d_out;

    cudaFuncSetAttribute(k_mm1, cudaFuncAttributeMaxDynamicSharedMemorySize, SMEM1);
    cudaFuncSetAttribute(k_mm2, cudaFuncAttributeMaxDynamicSharedMemorySize, SMEM1);

    k_fused<<<2048, 256>>>(emb, guid);
    k_mm1<<<dim3(64, 2), 256, SMEM1>>>();
    k_mm2<<<dim3(64, 4), 256, SMEM1>>>();
    k_out<<<dim3(256, 4), 256>>>(out);
}